// round 4
// baseline (speedup 1.0000x reference)
#include <cuda_runtime.h>
#include <cuda_bf16.h>
#include <math.h>
#include <stdint.h>

#define B_ROWS 65536
#define S_DIM  376
#define A_DIM  17
#define H1_DIM 400
#define H2_DIM 300
#define K_FLOWS 15
#define HEAD_N 559

#define KP0 384   // padded S_DIM
#define NB1 448   // padded H1_DIM  (= K of layer 2)
#define KP1 448
#define NB2 320   // padded H2_DIM  (= K of layer 3)
#define KP2 320
#define NB3 576   // padded HEAD_N

// ---------------- scratch (static device globals; no allocation) -------------
__device__ __nv_bfloat16 g_xhi[(size_t)B_ROWS * KP0];
__device__ __nv_bfloat16 g_xlo[(size_t)B_ROWS * KP0];
__device__ __nv_bfloat16 g_h1hi[(size_t)B_ROWS * NB1];
__device__ __nv_bfloat16 g_h1lo[(size_t)B_ROWS * NB1];
__device__ __nv_bfloat16 g_h2hi[(size_t)B_ROWS * NB2];
__device__ __nv_bfloat16 g_h2lo[(size_t)B_ROWS * NB2];
__device__ float         g_heads[(size_t)B_ROWS * NB3];

__device__ __nv_bfloat16 g_W1hi[KP0 * NB1], g_W1lo[KP0 * NB1];
__device__ __nv_bfloat16 g_W2hi[KP1 * NB2], g_W2lo[KP1 * NB2];
__device__ __nv_bfloat16 g_Whhi[KP2 * NB3], g_Whlo[KP2 * NB3];
__device__ float         g_bh[HEAD_N];

// ---------------- small helpers ----------------------------------------------
__device__ __forceinline__ uint32_t smem_u32(const void* p) {
    return (uint32_t)__cvta_generic_to_shared(p);
}
__device__ __forceinline__ void cp16(uint32_t dst, const void* src) {
    asm volatile("cp.async.cg.shared.global [%0], [%1], 16;\n" :: "r"(dst), "l"(src));
}
__device__ __forceinline__ void cp_commit() {
    asm volatile("cp.async.commit_group;\n" ::);
}
__device__ __forceinline__ void ldsm_x4(uint32_t* r, uint32_t addr) {
    asm volatile("ldmatrix.sync.aligned.m8n8.x4.shared.b16 {%0,%1,%2,%3}, [%4];\n"
                 : "=r"(r[0]), "=r"(r[1]), "=r"(r[2]), "=r"(r[3]) : "r"(addr));
}
__device__ __forceinline__ void ldsm_x4t(uint32_t* r, uint32_t addr) {
    asm volatile("ldmatrix.sync.aligned.m8n8.x4.trans.shared.b16 {%0,%1,%2,%3}, [%4];\n"
                 : "=r"(r[0]), "=r"(r[1]), "=r"(r[2]), "=r"(r[3]) : "r"(addr));
}
__device__ __forceinline__ void mma16816(float* c, const uint32_t* a, uint32_t b0, uint32_t b1) {
    asm volatile("mma.sync.aligned.m16n8k16.row.col.f32.bf16.bf16.f32 "
                 "{%0,%1,%2,%3}, {%4,%5,%6,%7}, {%8,%9}, {%0,%1,%2,%3};\n"
                 : "+f"(c[0]), "+f"(c[1]), "+f"(c[2]), "+f"(c[3])
                 : "r"(a[0]), "r"(a[1]), "r"(a[2]), "r"(a[3]), "r"(b0), "r"(b1));
}

// ---------------- conversion / packing kernels --------------------------------
__global__ void convert_x(const float* __restrict__ x,
                          __nv_bfloat16* __restrict__ hi, __nv_bfloat16* __restrict__ lo)
{
    size_t idx = (size_t)blockIdx.x * blockDim.x + threadIdx.x;
    if (idx >= (size_t)B_ROWS * KP0) return;
    int m = (int)(idx / KP0);
    int k = (int)(idx - (size_t)m * KP0);
    float v = (k < S_DIM) ? x[(size_t)m * S_DIM + k] : 0.0f;
    __nv_bfloat16 h = __float2bfloat16(v);
    hi[idx] = h;
    lo[idx] = __float2bfloat16(v - __bfloat162float(h));
}

__global__ void convert_w(const float* __restrict__ W, int K, int N,
                          __nv_bfloat16* __restrict__ hi, __nv_bfloat16* __restrict__ lo,
                          int KPd, int NBd)
{
    int idx = blockIdx.x * blockDim.x + threadIdx.x;
    if (idx >= KPd * NBd) return;
    int k = idx / NBd, n = idx - k * NBd;
    float v = (k < K && n < N) ? W[(size_t)k * N + n] : 0.0f;
    __nv_bfloat16 h = __float2bfloat16(v);
    hi[idx] = h;
    lo[idx] = __float2bfloat16(v - __bfloat162float(h));
}

__global__ void pack_heads(const float* __restrict__ Wmu, const float* __restrict__ bmu,
                           const float* __restrict__ Wlv, const float* __restrict__ blv,
                           const float* __restrict__ Wu,  const float* __restrict__ bu,
                           const float* __restrict__ Ww,  const float* __restrict__ bw,
                           const float* __restrict__ Wb,  const float* __restrict__ bb)
{
    int idx = blockIdx.x * blockDim.x + threadIdx.x;
    if (idx < KP2 * NB3) {
        int k = idx / NB3, c = idx - k * NB3;
        float v = 0.0f;
        if (k < H2_DIM) {
            if      (c < 17)  v = Wmu[k * 17  + c];
            else if (c < 34)  v = Wlv[k * 17  + (c - 17)];
            else if (c < 289) v = Wu [k * 255 + (c - 34)];
            else if (c < 544) v = Ww [k * 255 + (c - 289)];
            else if (c < 559) v = Wb [k * 15  + (c - 544)];
        }
        __nv_bfloat16 h = __float2bfloat16(v);
        g_Whhi[idx] = h;
        g_Whlo[idx] = __float2bfloat16(v - __bfloat162float(h));
    }
    if (idx < HEAD_N) {
        int c = idx;
        float v;
        if      (c < 17)  v = bmu[c];
        else if (c < 34)  v = blv[c - 17];
        else if (c < 289) v = bu [c - 34];
        else if (c < 544) v = bw [c - 289];
        else              v = bb [c - 544];
        g_bh[c] = v;
    }
}

// ---------------- tensor-core GEMM (mma.sync, 3-term bf16 split) --------------
// Block tile 256(M) x 64(N) x 32(K); 8 warps: 4 over M (64 rows each),
// 2 over N (32 cols each); warp tile 64x32. 4-stage cp.async pipeline.
//   D = Ahi*Bhi + Ahi*Blo + Alo*Bhi  (fp32 accum)
// SMEM per stage: As 256x64 bf16 (hi k-cols 0-31, lo 32-63) = 32KB
//                 Bs 32x128 bf16 (hi n-cols 0-63, lo 64-127) = 8KB
#define STAGES 4
#define STAGE_BYTES (32768 + 8192)

template <int OUT>
__global__ __launch_bounds__(256, 1) void gemm_mma(
    const __nv_bfloat16* __restrict__ Ahi, const __nv_bfloat16* __restrict__ Alo, int lda,
    const __nv_bfloat16* __restrict__ Bhi, const __nv_bfloat16* __restrict__ Blo, int ldb,
    const float* __restrict__ bias, int N,
    float* __restrict__ Cf,
    __nv_bfloat16* __restrict__ Chi, __nv_bfloat16* __restrict__ Clo, int ldc)
{
    extern __shared__ char smem[];
    const uint32_t sb = smem_u32(smem);

    const int tid  = threadIdx.x;
    const int lane = tid & 31;
    const int wid  = tid >> 5;
    const int wm   = wid & 3;      // 4 warps over M (64 rows each)
    const int wn   = wid >> 2;     // 2 warps over N (32 cols each)
    const int m0   = blockIdx.y * 256;
    const int n0   = blockIdx.x * 64;
    const int KT   = lda / 32;

    float acc[4][4][4];
#pragma unroll
    for (int i = 0; i < 4; i++)
#pragma unroll
        for (int j = 0; j < 4; j++)
#pragma unroll
            for (int q = 0; q < 4; q++) acc[i][j][q] = 0.0f;

    auto load_stage = [&](int s, int kt) {
        const uint32_t stA = sb + s * STAGE_BYTES;
        const uint32_t stB = stA + 32768;
        // A: 2048 chunks of 16B (256 rows x 8; c8 0-3 hi, 4-7 lo)
#pragma unroll
        for (int q = 0; q < 8; q++) {
            int g   = tid + 256 * q;
            int row = g >> 3;
            int c8  = g & 7;
            const __nv_bfloat16* src =
                (c8 < 4 ? Ahi : Alo) + (size_t)(m0 + row) * lda + kt * 32 + (c8 & 3) * 8;
            cp16(stA + row * 128 + ((c8 ^ row) & 7) * 16, src);
        }
        // B: 512 chunks (32 rows x 16; c16 0-7 hi, 8-15 lo)
#pragma unroll
        for (int q = 0; q < 2; q++) {
            int g   = tid + 256 * q;
            int row = g >> 4;
            int c16 = g & 15;
            const __nv_bfloat16* src =
                (c16 < 8 ? Bhi : Blo) + (size_t)(kt * 32 + row) * ldb + n0 + (c16 & 7) * 8;
            int phys = (c16 & 8) | ((c16 ^ row) & 7);
            cp16(stB + row * 256 + phys * 16, src);
        }
        cp_commit();
    };

    load_stage(0, 0);
    load_stage(1, 1);
    load_stage(2, 2);

    for (int c = 0; c < KT; c++) {
        const int s = c & (STAGES - 1);
        asm volatile("cp.async.wait_group 2;" ::: "memory");
        __syncthreads();

        if (c + 3 < KT) load_stage((c + 3) & (STAGES - 1), c + 3);
        else            cp_commit();

        const uint32_t stA = sb + s * STAGE_BYTES;
        const uint32_t stB = stA + 32768;

#pragma unroll
        for (int kk = 0; kk < 2; kk++) {
            uint32_t ah[4][4], al[4][4], bh[2][4], bl[2][4];
            {
                int rbase = (lane & 15);
                int half  = (lane >> 4);
#pragma unroll
                for (int mi = 0; mi < 4; mi++) {
                    int r   = wm * 64 + mi * 16 + rbase;
                    int c8h = kk * 2 + half;
                    int c8l = 4 + kk * 2 + half;
                    ldsm_x4(ah[mi], stA + r * 128 + ((c8h ^ r) & 7) * 16);
                    ldsm_x4(al[mi], stA + r * 128 + ((c8l ^ r) & 7) * 16);
                }
            }
            {
                int row  = kk * 16 + (lane & 15);
                int half = (lane >> 4);
#pragma unroll
                for (int ni = 0; ni < 2; ni++) {
                    int c16h = wn * 4 + ni * 2 + half;
                    int c16l = 8 + c16h;
                    int ph = (c16h & 8) | ((c16h ^ row) & 7);
                    int pl = (c16l & 8) | ((c16l ^ row) & 7);
                    ldsm_x4t(bh[ni], stB + row * 256 + ph * 16);
                    ldsm_x4t(bl[ni], stB + row * 256 + pl * 16);
                }
            }
#pragma unroll
            for (int mi = 0; mi < 4; mi++) {
#pragma unroll
                for (int n8 = 0; n8 < 4; n8++) {
                    int ni = n8 >> 1, j = (n8 & 1) * 2;
                    mma16816(acc[mi][n8], ah[mi], bh[ni][j], bh[ni][j + 1]); // hi*hi
                    mma16816(acc[mi][n8], ah[mi], bl[ni][j], bl[ni][j + 1]); // hi*lo
                    mma16816(acc[mi][n8], al[mi], bh[ni][j], bh[ni][j + 1]); // lo*hi
                }
            }
        }
        __syncthreads();
    }

    // ---- epilogue ----
    const int lr = lane >> 2;          // 0..7
    const int lc = (lane & 3) * 2;     // 0,2,4,6
#pragma unroll
    for (int mi = 0; mi < 4; mi++) {
#pragma unroll
        for (int n8 = 0; n8 < 4; n8++) {
            int col = n0 + wn * 32 + n8 * 8 + lc;
            float b0 = (col     < N) ? bias[col]     : 0.0f;
            float b1 = (col + 1 < N) ? bias[col + 1] : 0.0f;
#pragma unroll
            for (int h = 0; h < 2; h++) {
                int row = m0 + wm * 64 + mi * 16 + h * 8 + lr;
                float v0 = acc[mi][n8][2 * h + 0] + b0;
                float v1 = acc[mi][n8][2 * h + 1] + b1;
                if (OUT == 1) {
                    v0 = (col     < N) ? fmaxf(v0, 0.0f) : 0.0f;
                    v1 = (col + 1 < N) ? fmaxf(v1, 0.0f) : 0.0f;
                    __nv_bfloat16 h0 = __float2bfloat16(v0);
                    __nv_bfloat16 h1 = __float2bfloat16(v1);
                    __nv_bfloat162 hp; hp.x = h0; hp.y = h1;
                    __nv_bfloat162 lp;
                    lp.x = __float2bfloat16(v0 - __bfloat162float(h0));
                    lp.y = __float2bfloat16(v1 - __bfloat162float(h1));
                    *reinterpret_cast<__nv_bfloat162*>(&Chi[(size_t)row * ldc + col]) = hp;
                    *reinterpret_cast<__nv_bfloat162*>(&Clo[(size_t)row * ldc + col]) = lp;
                } else {
                    float2 f2; f2.x = v0; f2.y = v1;
                    *reinterpret_cast<float2*>(&Cf[(size_t)row * ldc + col]) = f2;
                }
            }
        }
    }
}

// ---------------- flow chain + sampling + log-prob epilogue ------------------
__global__ __launch_bounds__(256) void flow_kernel(
    const float* __restrict__ eps, float* __restrict__ out)
{
    const int warp = (blockIdx.x * blockDim.x + threadIdx.x) >> 5;
    const int lane = threadIdx.x & 31;
    if (warp >= B_ROWS) return;

    const float* hr = g_heads + (size_t)warp * NB3;
    const bool act = (lane < A_DIM);

    float mu = 0.0f, lv = 0.0f, e = 0.0f;
    if (act) {
        mu = tanhf(hr[lane]);
        lv = tanhf(hr[17 + lane]);
        e  = eps[(size_t)warp * A_DIM + lane];
    }
    float z = mu + expf(lv) * e;
    float ldj = 0.0f;

    for (int k = 0; k < K_FLOWS; k++) {
        float u = 0.0f, w = 0.0f;
        if (act) {
            u = hr[34  + k * A_DIM + lane];
            w = hr[289 + k * A_DIM + lane];
        }
        float bk = hr[544 + k];

        float uw  = w * u;
        float wns = w * w;
        float wz  = w * z;
#pragma unroll
        for (int s = 16; s; s >>= 1) {
            uw  += __shfl_xor_sync(0xffffffffu, uw,  s);
            wns += __shfl_xor_sync(0xffffffffu, wns, s);
            wz  += __shfl_xor_sync(0xffffffffu, wz,  s);
        }
        float sp   = fmaxf(uw, 0.0f) + log1pf(expf(-fabsf(uw)));
        float m_uw = -1.0f + sp;
        float scale = (m_uw - uw) / wns;
        float u_hat = u + scale * w;
        float t = tanhf(wz + bk);
        z += u_hat * t;
        float psi_u = m_uw * (1.0f - t * t);
        ldj += logf(fabsf(1.0f + psi_u));
    }

    if (act) out[(size_t)warp * A_DIM + lane] = z;

    float lp = act ? (-0.5f * e * e - lv) : 0.0f;
#pragma unroll
    for (int s = 16; s; s >>= 1) lp += __shfl_xor_sync(0xffffffffu, lp, s);
    lp -= 0.5f * (float)A_DIM * 1.8378770664093453f;

    if (lane == 0) {
        float lpf = lp - ldj;
        out[(size_t)B_ROWS * A_DIM + warp]          = expf(lpf);
        out[(size_t)B_ROWS * A_DIM + B_ROWS + warp] = lpf;
    }
}

// ---------------- launch ------------------------------------------------------
extern "C" void kernel_launch(void* const* d_in, const int* in_sizes, int n_in,
                              void* d_out, int out_size)
{
    (void)in_sizes; (void)n_in; (void)out_size;

    const float* x   = (const float*)d_in[0];
    const float* eps = (const float*)d_in[1];
    const float* W1  = (const float*)d_in[2];
    const float* b1  = (const float*)d_in[3];
    const float* W2  = (const float*)d_in[4];
    const float* b2  = (const float*)d_in[5];
    const float* Wmu = (const float*)d_in[6];
    const float* bmu = (const float*)d_in[7];
    const float* Wlv = (const float*)d_in[8];
    const float* blv = (const float*)d_in[9];
    const float* Wu  = (const float*)d_in[10];
    const float* bu  = (const float*)d_in[11];
    const float* Ww  = (const float*)d_in[12];
    const float* bw  = (const float*)d_in[13];
    const float* Wb  = (const float*)d_in[14];
    const float* bb  = (const float*)d_in[15];
    float* out = (float*)d_out;

    __nv_bfloat16 *xhi, *xlo, *h1hi, *h1lo, *h2hi, *h2lo;
    __nv_bfloat16 *w1hi, *w1lo, *w2hi, *w2lo, *whhi, *whlo;
    float *hdp, *bhp;
    cudaGetSymbolAddress((void**)&xhi,  g_xhi);
    cudaGetSymbolAddress((void**)&xlo,  g_xlo);
    cudaGetSymbolAddress((void**)&h1hi, g_h1hi);
    cudaGetSymbolAddress((void**)&h1lo, g_h1lo);
    cudaGetSymbolAddress((void**)&h2hi, g_h2hi);
    cudaGetSymbolAddress((void**)&h2lo, g_h2lo);
    cudaGetSymbolAddress((void**)&w1hi, g_W1hi);
    cudaGetSymbolAddress((void**)&w1lo, g_W1lo);
    cudaGetSymbolAddress((void**)&w2hi, g_W2hi);
    cudaGetSymbolAddress((void**)&w2lo, g_W2lo);
    cudaGetSymbolAddress((void**)&whhi, g_Whhi);
    cudaGetSymbolAddress((void**)&whlo, g_Whlo);
    cudaGetSymbolAddress((void**)&hdp,  g_heads);
    cudaGetSymbolAddress((void**)&bhp,  g_bh);

    convert_x<<<(int)(((size_t)B_ROWS * KP0 + 255) / 256), 256>>>(x, xhi, xlo);
    convert_w<<<(KP0 * NB1 + 255) / 256, 256>>>(W1, S_DIM,  H1_DIM, w1hi, w1lo, KP0, NB1);
    convert_w<<<(KP1 * NB2 + 255) / 256, 256>>>(W2, H1_DIM, H2_DIM, w2hi, w2lo, KP1, NB2);
    pack_heads<<<(KP2 * NB3 + 255) / 256, 256>>>(Wmu, bmu, Wlv, blv, Wu, bu, Ww, bw, Wb, bb);

    const int smem_bytes = STAGES * STAGE_BYTES;   // 163840
    cudaFuncSetAttribute(gemm_mma<1>, cudaFuncAttributeMaxDynamicSharedMemorySize, smem_bytes);
    cudaFuncSetAttribute(gemm_mma<0>, cudaFuncAttributeMaxDynamicSharedMemorySize, smem_bytes);

    dim3 blk(256);
    // layer 1: [65536,384] x [384,448] -> h1 (relu, split)
    gemm_mma<1><<<dim3(NB1 / 64, B_ROWS / 256), blk, smem_bytes>>>(
        xhi, xlo, KP0, w1hi, w1lo, NB1, b1, H1_DIM,
        nullptr, h1hi, h1lo, NB1);
    // layer 2: [65536,448] x [448,320] -> h2 (relu, split)
    gemm_mma<1><<<dim3(NB2 / 64, B_ROWS / 256), blk, smem_bytes>>>(
        h1hi, h1lo, KP1, w2hi, w2lo, NB2, b2, H2_DIM,
        nullptr, h2hi, h2lo, NB2);
    // heads: [65536,320] x [320,576] -> fp32
    gemm_mma<0><<<dim3(NB3 / 64, B_ROWS / 256), blk, smem_bytes>>>(
        h2hi, h2lo, KP2, whhi, whlo, NB3, bhp, HEAD_N,
        hdp, nullptr, nullptr, NB3);

    flow_kernel<<<(B_ROWS * 32) / 256, 256>>>(eps, out);
}

// round 5
// speedup vs baseline: 1.1567x; 1.1567x over previous
#include <cuda_runtime.h>
#include <cuda_bf16.h>
#include <math.h>
#include <stdint.h>

#define B_ROWS 65536
#define S_DIM  376
#define A_DIM  17
#define H1_DIM 400
#define H2_DIM 300
#define K_FLOWS 15
#define HEAD_N 559

#define KP0 384   // padded S_DIM
#define NB1 448   // padded H1_DIM  (= K stride of layer 2)
#define KI1 416   // K iterations for layer 2 (cols 400..415 are zero, 416..447 skipped)
#define NB2 320   // padded H2_DIM  (= K of layer 3)
#define KP2 320
#define NB3 576   // padded HEAD_N

// ---------------- scratch (static device globals; no allocation) -------------
__device__ __nv_bfloat16 g_xhi[(size_t)B_ROWS * KP0];
__device__ __nv_bfloat16 g_xlo[(size_t)B_ROWS * KP0];
__device__ __nv_bfloat16 g_h1hi[(size_t)B_ROWS * NB1];
__device__ __nv_bfloat16 g_h1lo[(size_t)B_ROWS * NB1];
__device__ __nv_bfloat16 g_h2hi[(size_t)B_ROWS * NB2];
__device__ __nv_bfloat16 g_h2lo[(size_t)B_ROWS * NB2];
__device__ float         g_heads[(size_t)B_ROWS * NB3];

__device__ __nv_bfloat16 g_W1hi[KP0 * NB1], g_W1lo[KP0 * NB1];
__device__ __nv_bfloat16 g_W2hi[NB1 * NB2], g_W2lo[NB1 * NB2];
__device__ __nv_bfloat16 g_Whhi[KP2 * NB3], g_Whlo[KP2 * NB3];
__device__ float         g_bh[HEAD_N];

// ---------------- small helpers ----------------------------------------------
__device__ __forceinline__ uint32_t smem_u32(const void* p) {
    return (uint32_t)__cvta_generic_to_shared(p);
}
__device__ __forceinline__ void cp16(uint32_t dst, const void* src) {
    asm volatile("cp.async.cg.shared.global [%0], [%1], 16;\n" :: "r"(dst), "l"(src));
}
__device__ __forceinline__ void cp_commit() {
    asm volatile("cp.async.commit_group;\n" ::);
}
__device__ __forceinline__ void ldsm_x4(uint32_t* r, uint32_t addr) {
    asm volatile("ldmatrix.sync.aligned.m8n8.x4.shared.b16 {%0,%1,%2,%3}, [%4];\n"
                 : "=r"(r[0]), "=r"(r[1]), "=r"(r[2]), "=r"(r[3]) : "r"(addr));
}
__device__ __forceinline__ void ldsm_x4t(uint32_t* r, uint32_t addr) {
    asm volatile("ldmatrix.sync.aligned.m8n8.x4.trans.shared.b16 {%0,%1,%2,%3}, [%4];\n"
                 : "=r"(r[0]), "=r"(r[1]), "=r"(r[2]), "=r"(r[3]) : "r"(addr));
}
__device__ __forceinline__ void mma16816(float* c, const uint32_t* a, uint32_t b0, uint32_t b1) {
    asm volatile("mma.sync.aligned.m16n8k16.row.col.f32.bf16.bf16.f32 "
                 "{%0,%1,%2,%3}, {%4,%5,%6,%7}, {%8,%9}, {%0,%1,%2,%3};\n"
                 : "+f"(c[0]), "+f"(c[1]), "+f"(c[2]), "+f"(c[3])
                 : "r"(a[0]), "r"(a[1]), "r"(a[2]), "r"(a[3]), "r"(b0), "r"(b1));
}

// ---------------- conversion / packing kernels --------------------------------
__global__ void convert_x(const float* __restrict__ x,
                          __nv_bfloat16* __restrict__ hi, __nv_bfloat16* __restrict__ lo)
{
    size_t idx = (size_t)blockIdx.x * blockDim.x + threadIdx.x;
    if (idx >= (size_t)B_ROWS * KP0) return;
    int m = (int)(idx / KP0);
    int k = (int)(idx - (size_t)m * KP0);
    float v = (k < S_DIM) ? x[(size_t)m * S_DIM + k] : 0.0f;
    __nv_bfloat16 h = __float2bfloat16(v);
    hi[idx] = h;
    lo[idx] = __float2bfloat16(v - __bfloat162float(h));
}

__global__ void convert_w(const float* __restrict__ W, int K, int N,
                          __nv_bfloat16* __restrict__ hi, __nv_bfloat16* __restrict__ lo,
                          int KPd, int NBd)
{
    int idx = blockIdx.x * blockDim.x + threadIdx.x;
    if (idx >= KPd * NBd) return;
    int k = idx / NBd, n = idx - k * NBd;
    float v = (k < K && n < N) ? W[(size_t)k * N + n] : 0.0f;
    __nv_bfloat16 h = __float2bfloat16(v);
    hi[idx] = h;
    lo[idx] = __float2bfloat16(v - __bfloat162float(h));
}

__global__ void pack_heads(const float* __restrict__ Wmu, const float* __restrict__ bmu,
                           const float* __restrict__ Wlv, const float* __restrict__ blv,
                           const float* __restrict__ Wu,  const float* __restrict__ bu,
                           const float* __restrict__ Ww,  const float* __restrict__ bw,
                           const float* __restrict__ Wb,  const float* __restrict__ bb)
{
    int idx = blockIdx.x * blockDim.x + threadIdx.x;
    if (idx < KP2 * NB3) {
        int k = idx / NB3, c = idx - k * NB3;
        float v = 0.0f;
        if (k < H2_DIM) {
            if      (c < 17)  v = Wmu[k * 17  + c];
            else if (c < 34)  v = Wlv[k * 17  + (c - 17)];
            else if (c < 289) v = Wu [k * 255 + (c - 34)];
            else if (c < 544) v = Ww [k * 255 + (c - 289)];
            else if (c < 559) v = Wb [k * 15  + (c - 544)];
        }
        __nv_bfloat16 h = __float2bfloat16(v);
        g_Whhi[idx] = h;
        g_Whlo[idx] = __float2bfloat16(v - __bfloat162float(h));
    }
    if (idx < HEAD_N) {
        int c = idx;
        float v;
        if      (c < 17)  v = bmu[c];
        else if (c < 34)  v = blv[c - 17];
        else if (c < 289) v = bu [c - 34];
        else if (c < 544) v = bw [c - 289];
        else              v = bb [c - 544];
        g_bh[c] = v;
    }
}

// ---------------- tensor-core GEMM (mma.sync, 3-term bf16 split) --------------
// Block tile 128(M) x 64(N) x 32(K); 8 warps: 4 over M x 2 over N, warp 32x32.
// 4-stage cp.async ring, wait_group 2, one __syncthreads per K-chunk.
//   D = Ahi*Bhi + Ahi*Blo + Alo*Bhi  (fp32 accum)
// SMEM/stage: As 128x64 bf16 (hi k 0-31, lo 32-63) = 16KB; Bs 32x128 bf16 = 8KB.
#define STAGES 4
#define A_BYTES 16384
#define STAGE_BYTES 24576

template <int OUT>
__global__ __launch_bounds__(256, 2) void gemm_mma(
    const __nv_bfloat16* __restrict__ Ahi, const __nv_bfloat16* __restrict__ Alo,
    int lda, int Kiter,
    const __nv_bfloat16* __restrict__ Bhi, const __nv_bfloat16* __restrict__ Blo, int ldb,
    const float* __restrict__ bias, int N,
    float* __restrict__ Cf,
    __nv_bfloat16* __restrict__ Chi, __nv_bfloat16* __restrict__ Clo, int ldc)
{
    extern __shared__ char smem[];
    const uint32_t sb = smem_u32(smem);

    const int tid  = threadIdx.x;
    const int lane = tid & 31;
    const int wid  = tid >> 5;
    const int wm   = wid & 3;      // 4 warps over M (32 rows each)
    const int wn   = wid >> 2;     // 2 warps over N (32 cols each)
    const int m0   = blockIdx.y * 128;
    const int n0   = blockIdx.x * 64;
    const int KT   = Kiter / 32;

    float acc[2][4][4];
#pragma unroll
    for (int i = 0; i < 2; i++)
#pragma unroll
        for (int j = 0; j < 4; j++)
#pragma unroll
            for (int q = 0; q < 4; q++) acc[i][j][q] = 0.0f;

    auto load_stage = [&](int s, int kt) {
        const uint32_t stA = sb + s * STAGE_BYTES;
        const uint32_t stB = stA + A_BYTES;
        // A: 1024 chunks of 16B (128 rows x 8; c8 0-3 hi, 4-7 lo)
#pragma unroll
        for (int q = 0; q < 4; q++) {
            int g   = tid + 256 * q;
            int row = g >> 3;
            int c8  = g & 7;
            const __nv_bfloat16* src =
                (c8 < 4 ? Ahi : Alo) + (size_t)(m0 + row) * lda + kt * 32 + (c8 & 3) * 8;
            cp16(stA + row * 128 + ((c8 ^ row) & 7) * 16, src);
        }
        // B: 512 chunks (32 rows x 16; c16 0-7 hi, 8-15 lo)
#pragma unroll
        for (int q = 0; q < 2; q++) {
            int g   = tid + 256 * q;
            int row = g >> 4;
            int c16 = g & 15;
            const __nv_bfloat16* src =
                (c16 < 8 ? Bhi : Blo) + (size_t)(kt * 32 + row) * ldb + n0 + (c16 & 7) * 8;
            int phys = (c16 & 8) | ((c16 ^ row) & 7);
            cp16(stB + row * 256 + phys * 16, src);
        }
        cp_commit();
    };

    load_stage(0, 0);
    load_stage(1, 1);
    load_stage(2, 2);

    for (int c = 0; c < KT; c++) {
        const int s = c & (STAGES - 1);
        asm volatile("cp.async.wait_group 2;" ::: "memory");
        __syncthreads();

        if (c + 3 < KT) load_stage((c + 3) & (STAGES - 1), c + 3);
        else            cp_commit();

        const uint32_t stA = sb + s * STAGE_BYTES;
        const uint32_t stB = stA + A_BYTES;

#pragma unroll
        for (int kk = 0; kk < 2; kk++) {
            uint32_t ah[2][4], al[2][4], bh[2][4], bl[2][4];
            {
                int rbase = (lane & 15);
                int half  = (lane >> 4);
#pragma unroll
                for (int mi = 0; mi < 2; mi++) {
                    int r   = wm * 32 + mi * 16 + rbase;
                    int c8h = kk * 2 + half;
                    int c8l = 4 + kk * 2 + half;
                    ldsm_x4(ah[mi], stA + r * 128 + ((c8h ^ r) & 7) * 16);
                    ldsm_x4(al[mi], stA + r * 128 + ((c8l ^ r) & 7) * 16);
                }
            }
            {
                int row  = kk * 16 + (lane & 15);
                int half = (lane >> 4);
#pragma unroll
                for (int ni = 0; ni < 2; ni++) {
                    int c16h = wn * 4 + ni * 2 + half;
                    int c16l = 8 + c16h;
                    int ph = (c16h & 8) | ((c16h ^ row) & 7);
                    int pl = (c16l & 8) | ((c16l ^ row) & 7);
                    ldsm_x4t(bh[ni], stB + row * 256 + ph * 16);
                    ldsm_x4t(bl[ni], stB + row * 256 + pl * 16);
                }
            }
#pragma unroll
            for (int mi = 0; mi < 2; mi++) {
#pragma unroll
                for (int n8 = 0; n8 < 4; n8++) {
                    int ni = n8 >> 1, j = (n8 & 1) * 2;
                    mma16816(acc[mi][n8], ah[mi], bh[ni][j], bh[ni][j + 1]); // hi*hi
                    mma16816(acc[mi][n8], ah[mi], bl[ni][j], bl[ni][j + 1]); // hi*lo
                    mma16816(acc[mi][n8], al[mi], bh[ni][j], bh[ni][j + 1]); // lo*hi
                }
            }
        }
    }

    // ---- epilogue ----
    const int lr = lane >> 2;          // 0..7
    const int lc = (lane & 3) * 2;     // 0,2,4,6
#pragma unroll
    for (int mi = 0; mi < 2; mi++) {
#pragma unroll
        for (int n8 = 0; n8 < 4; n8++) {
            int col = n0 + wn * 32 + n8 * 8 + lc;
            float b0 = (col     < N) ? bias[col]     : 0.0f;
            float b1 = (col + 1 < N) ? bias[col + 1] : 0.0f;
#pragma unroll
            for (int h = 0; h < 2; h++) {
                int row = m0 + wm * 32 + mi * 16 + h * 8 + lr;
                float v0 = acc[mi][n8][2 * h + 0] + b0;
                float v1 = acc[mi][n8][2 * h + 1] + b1;
                if (OUT == 1) {
                    v0 = (col     < N) ? fmaxf(v0, 0.0f) : 0.0f;
                    v1 = (col + 1 < N) ? fmaxf(v1, 0.0f) : 0.0f;
                    __nv_bfloat16 h0 = __float2bfloat16(v0);
                    __nv_bfloat16 h1 = __float2bfloat16(v1);
                    __nv_bfloat162 hp; hp.x = h0; hp.y = h1;
                    __nv_bfloat162 lp;
                    lp.x = __float2bfloat16(v0 - __bfloat162float(h0));
                    lp.y = __float2bfloat16(v1 - __bfloat162float(h1));
                    *reinterpret_cast<__nv_bfloat162*>(&Chi[(size_t)row * ldc + col]) = hp;
                    *reinterpret_cast<__nv_bfloat162*>(&Clo[(size_t)row * ldc + col]) = lp;
                } else {
                    float2 f2; f2.x = v0; f2.y = v1;
                    *reinterpret_cast<float2*>(&Cf[(size_t)row * ldc + col]) = f2;
                }
            }
        }
    }
}

// ---------------- flow chain + sampling + log-prob epilogue ------------------
__global__ __launch_bounds__(256) void flow_kernel(
    const float* __restrict__ eps, float* __restrict__ out)
{
    const int warp = (blockIdx.x * blockDim.x + threadIdx.x) >> 5;
    const int lane = threadIdx.x & 31;
    if (warp >= B_ROWS) return;

    const float* hr = g_heads + (size_t)warp * NB3;
    const bool act = (lane < A_DIM);

    float mu = 0.0f, lv = 0.0f, e = 0.0f;
    if (act) {
        mu = tanhf(hr[lane]);
        lv = tanhf(hr[17 + lane]);
        e  = eps[(size_t)warp * A_DIM + lane];
    }
    float z = mu + expf(lv) * e;
    float ldj = 0.0f;

    for (int k = 0; k < K_FLOWS; k++) {
        float u = 0.0f, w = 0.0f;
        if (act) {
            u = hr[34  + k * A_DIM + lane];
            w = hr[289 + k * A_DIM + lane];
        }
        float bk = hr[544 + k];

        float uw  = w * u;
        float wns = w * w;
        float wz  = w * z;
#pragma unroll
        for (int s = 16; s; s >>= 1) {
            uw  += __shfl_xor_sync(0xffffffffu, uw,  s);
            wns += __shfl_xor_sync(0xffffffffu, wns, s);
            wz  += __shfl_xor_sync(0xffffffffu, wz,  s);
        }
        float sp   = fmaxf(uw, 0.0f) + log1pf(expf(-fabsf(uw)));
        float m_uw = -1.0f + sp;
        float scale = (m_uw - uw) / wns;
        float u_hat = u + scale * w;
        float t = tanhf(wz + bk);
        z += u_hat * t;
        float psi_u = m_uw * (1.0f - t * t);
        ldj += logf(fabsf(1.0f + psi_u));
    }

    if (act) out[(size_t)warp * A_DIM + lane] = z;

    float lp = act ? (-0.5f * e * e - lv) : 0.0f;
#pragma unroll
    for (int s = 16; s; s >>= 1) lp += __shfl_xor_sync(0xffffffffu, lp, s);
    lp -= 0.5f * (float)A_DIM * 1.8378770664093453f;

    if (lane == 0) {
        float lpf = lp - ldj;
        out[(size_t)B_ROWS * A_DIM + warp]          = expf(lpf);
        out[(size_t)B_ROWS * A_DIM + B_ROWS + warp] = lpf;
    }
}

// ---------------- launch ------------------------------------------------------
extern "C" void kernel_launch(void* const* d_in, const int* in_sizes, int n_in,
                              void* d_out, int out_size)
{
    (void)in_sizes; (void)n_in; (void)out_size;

    const float* x   = (const float*)d_in[0];
    const float* eps = (const float*)d_in[1];
    const float* W1  = (const float*)d_in[2];
    const float* b1  = (const float*)d_in[3];
    const float* W2  = (const float*)d_in[4];
    const float* b2  = (const float*)d_in[5];
    const float* Wmu = (const float*)d_in[6];
    const float* bmu = (const float*)d_in[7];
    const float* Wlv = (const float*)d_in[8];
    const float* blv = (const float*)d_in[9];
    const float* Wu  = (const float*)d_in[10];
    const float* bu  = (const float*)d_in[11];
    const float* Ww  = (const float*)d_in[12];
    const float* bw  = (const float*)d_in[13];
    const float* Wb  = (const float*)d_in[14];
    const float* bb  = (const float*)d_in[15];
    float* out = (float*)d_out;

    __nv_bfloat16 *xhi, *xlo, *h1hi, *h1lo, *h2hi, *h2lo;
    __nv_bfloat16 *w1hi, *w1lo, *w2hi, *w2lo, *whhi, *whlo;
    float *hdp, *bhp;
    cudaGetSymbolAddress((void**)&xhi,  g_xhi);
    cudaGetSymbolAddress((void**)&xlo,  g_xlo);
    cudaGetSymbolAddress((void**)&h1hi, g_h1hi);
    cudaGetSymbolAddress((void**)&h1lo, g_h1lo);
    cudaGetSymbolAddress((void**)&h2hi, g_h2hi);
    cudaGetSymbolAddress((void**)&h2lo, g_h2lo);
    cudaGetSymbolAddress((void**)&w1hi, g_W1hi);
    cudaGetSymbolAddress((void**)&w1lo, g_W1lo);
    cudaGetSymbolAddress((void**)&w2hi, g_W2hi);
    cudaGetSymbolAddress((void**)&w2lo, g_W2lo);
    cudaGetSymbolAddress((void**)&whhi, g_Whhi);
    cudaGetSymbolAddress((void**)&whlo, g_Whlo);
    cudaGetSymbolAddress((void**)&hdp,  g_heads);
    cudaGetSymbolAddress((void**)&bhp,  g_bh);

    convert_x<<<(int)(((size_t)B_ROWS * KP0 + 255) / 256), 256>>>(x, xhi, xlo);
    convert_w<<<(KP0 * NB1 + 255) / 256, 256>>>(W1, S_DIM,  H1_DIM, w1hi, w1lo, KP0, NB1);
    convert_w<<<(NB1 * NB2 + 255) / 256, 256>>>(W2, H1_DIM, H2_DIM, w2hi, w2lo, NB1, NB2);
    pack_heads<<<(KP2 * NB3 + 255) / 256, 256>>>(Wmu, bmu, Wlv, blv, Wu, bu, Ww, bw, Wb, bb);

    const int smem_bytes = STAGES * STAGE_BYTES;   // 98304
    cudaFuncSetAttribute(gemm_mma<1>, cudaFuncAttributeMaxDynamicSharedMemorySize, smem_bytes);
    cudaFuncSetAttribute(gemm_mma<0>, cudaFuncAttributeMaxDynamicSharedMemorySize, smem_bytes);

    dim3 blk(256);
    // layer 1: [65536,384] x [384,448] -> h1 (relu, split)
    gemm_mma<1><<<dim3(NB1 / 64, B_ROWS / 128), blk, smem_bytes>>>(
        xhi, xlo, KP0, KP0, w1hi, w1lo, NB1, b1, H1_DIM,
        nullptr, h1hi, h1lo, NB1);
    // layer 2: [65536,448(K=416)] x [448,320] -> h2 (relu, split)
    gemm_mma<1><<<dim3(NB2 / 64, B_ROWS / 128), blk, smem_bytes>>>(
        h1hi, h1lo, NB1, KI1, w2hi, w2lo, NB2, b2, H2_DIM,
        nullptr, h2hi, h2lo, NB2);
    // heads: [65536,320] x [320,576] -> fp32
    gemm_mma<0><<<dim3(NB3 / 64, B_ROWS / 128), blk, smem_bytes>>>(
        h2hi, h2lo, KP2, KP2, whhi, whlo, NB3, bhp, HEAD_N,
        hdp, nullptr, nullptr, NB3);

    flow_kernel<<<(B_ROWS * 32) / 256, 256>>>(eps, out);
}

// round 6
// speedup vs baseline: 1.9087x; 1.6501x over previous
#include <cuda_runtime.h>
#include <cuda_fp16.h>
#include <math.h>
#include <stdint.h>

#define B_ROWS 65536
#define S_DIM  376
#define A_DIM  17
#define H1_DIM 400
#define H2_DIM 300
#define K_FLOWS 15
#define HEAD_N 559

#define KP0 384   // padded S_DIM
#define NB1 448   // padded H1_DIM  (= K stride of layer 2)
#define KI1 416   // K iterations for layer 2 (cols 400..415 zero, 416..447 skipped)
#define NB2 320   // padded H2_DIM  (= K of layer 3)
#define KP2 320
#define NB3 576   // padded HEAD_N

// ---------------- scratch (static device globals; no allocation) -------------
__device__ __half g_x16[(size_t)B_ROWS * KP0];
__device__ __half g_h1[(size_t)B_ROWS * NB1];
__device__ __half g_h2[(size_t)B_ROWS * NB2];
__device__ float  g_heads[(size_t)B_ROWS * NB3];

__device__ __half g_W1[KP0 * NB1];
__device__ __half g_W2[NB1 * NB2];
__device__ __half g_Wh[KP2 * NB3];
__device__ float  g_bh[HEAD_N];

// ---------------- small helpers ----------------------------------------------
__device__ __forceinline__ uint32_t smem_u32(const void* p) {
    return (uint32_t)__cvta_generic_to_shared(p);
}
__device__ __forceinline__ void cp16(uint32_t dst, const void* src) {
    asm volatile("cp.async.cg.shared.global [%0], [%1], 16;\n" :: "r"(dst), "l"(src));
}
__device__ __forceinline__ void cp_commit() {
    asm volatile("cp.async.commit_group;\n" ::);
}
__device__ __forceinline__ void ldsm_x4(uint32_t* r, uint32_t addr) {
    asm volatile("ldmatrix.sync.aligned.m8n8.x4.shared.b16 {%0,%1,%2,%3}, [%4];\n"
                 : "=r"(r[0]), "=r"(r[1]), "=r"(r[2]), "=r"(r[3]) : "r"(addr));
}
__device__ __forceinline__ void ldsm_x4t(uint32_t* r, uint32_t addr) {
    asm volatile("ldmatrix.sync.aligned.m8n8.x4.trans.shared.b16 {%0,%1,%2,%3}, [%4];\n"
                 : "=r"(r[0]), "=r"(r[1]), "=r"(r[2]), "=r"(r[3]) : "r"(addr));
}
__device__ __forceinline__ void mma16816(float* c, const uint32_t* a, uint32_t b0, uint32_t b1) {
    asm volatile("mma.sync.aligned.m16n8k16.row.col.f32.f16.f16.f32 "
                 "{%0,%1,%2,%3}, {%4,%5,%6,%7}, {%8,%9}, {%0,%1,%2,%3};\n"
                 : "+f"(c[0]), "+f"(c[1]), "+f"(c[2]), "+f"(c[3])
                 : "r"(a[0]), "r"(a[1]), "r"(a[2]), "r"(a[3]), "r"(b0), "r"(b1));
}

// ---------------- conversion / packing kernels --------------------------------
__global__ void convert_x(const float* __restrict__ x, __half* __restrict__ o)
{
    size_t idx = (size_t)blockIdx.x * blockDim.x + threadIdx.x;
    if (idx >= (size_t)B_ROWS * KP0) return;
    int m = (int)(idx / KP0);
    int k = (int)(idx - (size_t)m * KP0);
    o[idx] = __float2half((k < S_DIM) ? x[(size_t)m * S_DIM + k] : 0.0f);
}

__global__ void convert_w(const float* __restrict__ W, int K, int N,
                          __half* __restrict__ o, int KPd, int NBd)
{
    int idx = blockIdx.x * blockDim.x + threadIdx.x;
    if (idx >= KPd * NBd) return;
    int k = idx / NBd, n = idx - k * NBd;
    o[idx] = __float2half((k < K && n < N) ? W[(size_t)k * N + n] : 0.0f);
}

__global__ void pack_heads(const float* __restrict__ Wmu, const float* __restrict__ bmu,
                           const float* __restrict__ Wlv, const float* __restrict__ blv,
                           const float* __restrict__ Wu,  const float* __restrict__ bu,
                           const float* __restrict__ Ww,  const float* __restrict__ bw,
                           const float* __restrict__ Wb,  const float* __restrict__ bb)
{
    int idx = blockIdx.x * blockDim.x + threadIdx.x;
    if (idx < KP2 * NB3) {
        int k = idx / NB3, c = idx - k * NB3;
        float v = 0.0f;
        if (k < H2_DIM) {
            if      (c < 17)  v = Wmu[k * 17  + c];
            else if (c < 34)  v = Wlv[k * 17  + (c - 17)];
            else if (c < 289) v = Wu [k * 255 + (c - 34)];
            else if (c < 544) v = Ww [k * 255 + (c - 289)];
            else if (c < 559) v = Wb [k * 15  + (c - 544)];
        }
        g_Wh[idx] = __float2half(v);
    }
    if (idx < HEAD_N) {
        int c = idx;
        float v;
        if      (c < 17)  v = bmu[c];
        else if (c < 34)  v = blv[c - 17];
        else if (c < 289) v = bu [c - 34];
        else if (c < 544) v = bw [c - 289];
        else              v = bb [c - 544];
        g_bh[c] = v;
    }
}

// ---------------- tensor-core GEMM (mma.sync fp16, single term) ---------------
// Block tile 256(M) x 64(N) x 32(K); 8 warps: 4 over M x 2 over N, warp 64x32.
// 4-stage cp.async ring (20KB/stage = 80KB total -> 2 CTAs/SM).
// SMEM/stage: As 256x32 fp16 (64B pitch, quad swizzle q^((r>>1)&3)) = 16KB
//             Bs 32x64 fp16 (128B pitch, quad swizzle c8^(r&7))     = 4KB
#define STAGES 4
#define A_BYTES 16384
#define STAGE_BYTES 20480

template <int OUT>
__global__ __launch_bounds__(256, 2) void gemm_mma(
    const __half* __restrict__ A, int lda, int Kiter,
    const __half* __restrict__ B, int ldb,
    const float* __restrict__ bias, int N,
    float* __restrict__ Cf, __half* __restrict__ Ch, int ldc)
{
    extern __shared__ char smem[];
    const uint32_t sb = smem_u32(smem);

    const int tid  = threadIdx.x;
    const int lane = tid & 31;
    const int wid  = tid >> 5;
    const int wm   = wid & 3;      // 4 warps over M (64 rows each)
    const int wn   = wid >> 2;     // 2 warps over N (32 cols each)
    const int m0   = blockIdx.y * 256;
    const int n0   = blockIdx.x * 64;
    const int KT   = Kiter / 32;

    float acc[4][4][4];
#pragma unroll
    for (int i = 0; i < 4; i++)
#pragma unroll
        for (int j = 0; j < 4; j++)
#pragma unroll
            for (int q = 0; q < 4; q++) acc[i][j][q] = 0.0f;

    auto load_stage = [&](int s, int kt) {
        const uint32_t stA = sb + s * STAGE_BYTES;
        const uint32_t stB = stA + A_BYTES;
        // A: 1024 chunks of 16B (256 rows x 4 quads)
#pragma unroll
        for (int q = 0; q < 4; q++) {
            int g   = tid + 256 * q;
            int row = g >> 2;
            int c4  = g & 3;
            const __half* src = A + (size_t)(m0 + row) * lda + kt * 32 + c4 * 8;
            cp16(stA + row * 64 + ((c4 ^ ((row >> 1) & 3)) * 16), src);
        }
        // B: 256 chunks (32 rows x 8 quads)
        {
            int row = tid >> 3;
            int c8  = tid & 7;
            const __half* src = B + (size_t)(kt * 32 + row) * ldb + n0 + c8 * 8;
            cp16(stB + row * 128 + ((c8 ^ (row & 7)) * 16), src);
        }
        cp_commit();
    };

    load_stage(0, 0);
    load_stage(1, 1);
    load_stage(2, 2);

    for (int c = 0; c < KT; c++) {
        const int s = c & (STAGES - 1);
        asm volatile("cp.async.wait_group 2;" ::: "memory");
        __syncthreads();

        if (c + 3 < KT) load_stage((c + 3) & (STAGES - 1), c + 3);
        else            cp_commit();

        const uint32_t stA = sb + s * STAGE_BYTES;
        const uint32_t stB = stA + A_BYTES;

#pragma unroll
        for (int kk = 0; kk < 2; kk++) {
            uint32_t ah[4][4], bh[2][4];
            {
                int rbase = (lane & 15);
                int q     = kk * 2 + (lane >> 4);   // 0..3
#pragma unroll
                for (int mi = 0; mi < 4; mi++) {
                    int r = wm * 64 + mi * 16 + rbase;
                    ldsm_x4(ah[mi], stA + r * 64 + ((q ^ ((r >> 1) & 3)) * 16));
                }
            }
            {
                int row  = kk * 16 + (lane & 15);
                int half = (lane >> 4);
#pragma unroll
                for (int ni = 0; ni < 2; ni++) {
                    int c8 = wn * 4 + ni * 2 + half;
                    ldsm_x4t(bh[ni], stB + row * 128 + ((c8 ^ (row & 7)) * 16));
                }
            }
#pragma unroll
            for (int mi = 0; mi < 4; mi++) {
#pragma unroll
                for (int n8 = 0; n8 < 4; n8++) {
                    int ni = n8 >> 1, j = (n8 & 1) * 2;
                    mma16816(acc[mi][n8], ah[mi], bh[ni][j], bh[ni][j + 1]);
                }
            }
        }
    }

    // ---- epilogue ----
    const int lr = lane >> 2;          // 0..7
    const int lc = (lane & 3) * 2;     // 0,2,4,6
#pragma unroll
    for (int mi = 0; mi < 4; mi++) {
#pragma unroll
        for (int n8 = 0; n8 < 4; n8++) {
            int col = n0 + wn * 32 + n8 * 8 + lc;
            float b0 = (col     < N) ? bias[col]     : 0.0f;
            float b1 = (col + 1 < N) ? bias[col + 1] : 0.0f;
#pragma unroll
            for (int h = 0; h < 2; h++) {
                int row = m0 + wm * 64 + mi * 16 + h * 8 + lr;
                float v0 = acc[mi][n8][2 * h + 0] + b0;
                float v1 = acc[mi][n8][2 * h + 1] + b1;
                if (OUT == 1) {
                    v0 = (col     < N) ? fmaxf(v0, 0.0f) : 0.0f;
                    v1 = (col + 1 < N) ? fmaxf(v1, 0.0f) : 0.0f;
                    __half2 hv; hv.x = __float2half(v0); hv.y = __float2half(v1);
                    *reinterpret_cast<__half2*>(&Ch[(size_t)row * ldc + col]) = hv;
                } else {
                    float2 f2; f2.x = v0; f2.y = v1;
                    *reinterpret_cast<float2*>(&Cf[(size_t)row * ldc + col]) = f2;
                }
            }
        }
    }
}

// ---------------- flow chain + sampling + log-prob epilogue ------------------
__global__ __launch_bounds__(256) void flow_kernel(
    const float* __restrict__ eps, float* __restrict__ out)
{
    const int warp = (blockIdx.x * blockDim.x + threadIdx.x) >> 5;
    const int lane = threadIdx.x & 31;
    if (warp >= B_ROWS) return;

    const float* hr = g_heads + (size_t)warp * NB3;
    const bool act = (lane < A_DIM);

    float mu = 0.0f, lv = 0.0f, e = 0.0f;
    if (act) {
        mu = tanhf(hr[lane]);
        lv = tanhf(hr[17 + lane]);
        e  = eps[(size_t)warp * A_DIM + lane];
    }
    float z = mu + expf(lv) * e;
    float ldj = 0.0f;

    for (int k = 0; k < K_FLOWS; k++) {
        float u = 0.0f, w = 0.0f;
        if (act) {
            u = hr[34  + k * A_DIM + lane];
            w = hr[289 + k * A_DIM + lane];
        }
        float bk = hr[544 + k];

        float uw  = w * u;
        float wns = w * w;
        float wz  = w * z;
#pragma unroll
        for (int s = 16; s; s >>= 1) {
            uw  += __shfl_xor_sync(0xffffffffu, uw,  s);
            wns += __shfl_xor_sync(0xffffffffu, wns, s);
            wz  += __shfl_xor_sync(0xffffffffu, wz,  s);
        }
        float sp   = fmaxf(uw, 0.0f) + log1pf(expf(-fabsf(uw)));
        float m_uw = -1.0f + sp;
        float scale = (m_uw - uw) / wns;
        float u_hat = u + scale * w;
        float t = tanhf(wz + bk);
        z += u_hat * t;
        float psi_u = m_uw * (1.0f - t * t);
        ldj += logf(fabsf(1.0f + psi_u));
    }

    if (act) out[(size_t)warp * A_DIM + lane] = z;

    float lp = act ? (-0.5f * e * e - lv) : 0.0f;
#pragma unroll
    for (int s = 16; s; s >>= 1) lp += __shfl_xor_sync(0xffffffffu, lp, s);
    lp -= 0.5f * (float)A_DIM * 1.8378770664093453f;

    if (lane == 0) {
        float lpf = lp - ldj;
        out[(size_t)B_ROWS * A_DIM + warp]          = expf(lpf);
        out[(size_t)B_ROWS * A_DIM + B_ROWS + warp] = lpf;
    }
}

// ---------------- launch ------------------------------------------------------
extern "C" void kernel_launch(void* const* d_in, const int* in_sizes, int n_in,
                              void* d_out, int out_size)
{
    (void)in_sizes; (void)n_in; (void)out_size;

    const float* x   = (const float*)d_in[0];
    const float* eps = (const float*)d_in[1];
    const float* W1  = (const float*)d_in[2];
    const float* b1  = (const float*)d_in[3];
    const float* W2  = (const float*)d_in[4];
    const float* b2  = (const float*)d_in[5];
    const float* Wmu = (const float*)d_in[6];
    const float* bmu = (const float*)d_in[7];
    const float* Wlv = (const float*)d_in[8];
    const float* blv = (const float*)d_in[9];
    const float* Wu  = (const float*)d_in[10];
    const float* bu  = (const float*)d_in[11];
    const float* Ww  = (const float*)d_in[12];
    const float* bw  = (const float*)d_in[13];
    const float* Wb  = (const float*)d_in[14];
    const float* bb  = (const float*)d_in[15];
    float* out = (float*)d_out;

    __half *x16, *h1, *h2, *w1, *w2, *wh;
    float *hdp, *bhp;
    cudaGetSymbolAddress((void**)&x16, g_x16);
    cudaGetSymbolAddress((void**)&h1,  g_h1);
    cudaGetSymbolAddress((void**)&h2,  g_h2);
    cudaGetSymbolAddress((void**)&w1,  g_W1);
    cudaGetSymbolAddress((void**)&w2,  g_W2);
    cudaGetSymbolAddress((void**)&wh,  g_Wh);
    cudaGetSymbolAddress((void**)&hdp, g_heads);
    cudaGetSymbolAddress((void**)&bhp, g_bh);

    convert_x<<<(int)(((size_t)B_ROWS * KP0 + 255) / 256), 256>>>(x, x16);
    convert_w<<<(KP0 * NB1 + 255) / 256, 256>>>(W1, S_DIM,  H1_DIM, w1, KP0, NB1);
    convert_w<<<(NB1 * NB2 + 255) / 256, 256>>>(W2, H1_DIM, H2_DIM, w2, NB1, NB2);
    pack_heads<<<(KP2 * NB3 + 255) / 256, 256>>>(Wmu, bmu, Wlv, blv, Wu, bu, Ww, bw, Wb, bb);

    const int smem_bytes = STAGES * STAGE_BYTES;   // 81920
    cudaFuncSetAttribute(gemm_mma<1>, cudaFuncAttributeMaxDynamicSharedMemorySize, smem_bytes);
    cudaFuncSetAttribute(gemm_mma<0>, cudaFuncAttributeMaxDynamicSharedMemorySize, smem_bytes);

    dim3 blk(256);
    // layer 1: [65536,384] x [384,448] -> h1 (relu)
    gemm_mma<1><<<dim3(NB1 / 64, B_ROWS / 256), blk, smem_bytes>>>(
        x16, KP0, KP0, w1, NB1, b1, H1_DIM, nullptr, h1, NB1);
    // layer 2: [65536,448(K=416)] x [448,320] -> h2 (relu)
    gemm_mma<1><<<dim3(NB2 / 64, B_ROWS / 256), blk, smem_bytes>>>(
        h1, NB1, KI1, w2, NB2, b2, H2_DIM, nullptr, h2, NB2);
    // heads: [65536,320] x [320,576] -> fp32
    gemm_mma<0><<<dim3(NB3 / 64, B_ROWS / 256), blk, smem_bytes>>>(
        h2, KP2, KP2, wh, NB3, bhp, HEAD_N, hdp, nullptr, NB3);

    flow_kernel<<<(B_ROWS * 32) / 256, 256>>>(eps, out);
}

// round 7
// speedup vs baseline: 2.3482x; 1.2303x over previous
#include <cuda_runtime.h>
#include <cuda_fp16.h>
#include <math.h>
#include <stdint.h>

#define B_ROWS 65536
#define S_DIM  376
#define A_DIM  17
#define H1_DIM 400
#define H2_DIM 300
#define K_FLOWS 15
#define HEAD_N 559

#define KP0 384   // padded S_DIM
#define NB1 448   // padded H1_DIM  (= K stride of layer 2)
#define KI1 416   // K iterations for layer 2 (cols 400..415 zero, 416..447 skipped)
#define NB2 320   // padded H2_DIM  (= K of layer 3)
#define KP2 320
#define NB3 576   // padded HEAD_N

// ---------------- scratch (static device globals; no allocation) -------------
__device__ __half g_x16[(size_t)B_ROWS * KP0];
__device__ __half g_h1[(size_t)B_ROWS * NB1];
__device__ __half g_h2[(size_t)B_ROWS * NB2];
__device__ float  g_heads[(size_t)B_ROWS * NB3];

__device__ __half g_W1[KP0 * NB1];
__device__ __half g_W2[NB1 * NB2];
__device__ __half g_Wh[KP2 * NB3];
__device__ float  g_bh[HEAD_N];

// ---------------- small helpers ----------------------------------------------
__device__ __forceinline__ uint32_t smem_u32(const void* p) {
    return (uint32_t)__cvta_generic_to_shared(p);
}
__device__ __forceinline__ void cp16(uint32_t dst, const void* src) {
    asm volatile("cp.async.cg.shared.global [%0], [%1], 16;\n" :: "r"(dst), "l"(src));
}
__device__ __forceinline__ void cp_commit() {
    asm volatile("cp.async.commit_group;\n" ::);
}
__device__ __forceinline__ void ldsm_x4(uint32_t* r, uint32_t addr) {
    asm volatile("ldmatrix.sync.aligned.m8n8.x4.shared.b16 {%0,%1,%2,%3}, [%4];\n"
                 : "=r"(r[0]), "=r"(r[1]), "=r"(r[2]), "=r"(r[3]) : "r"(addr));
}
__device__ __forceinline__ void ldsm_x4t(uint32_t* r, uint32_t addr) {
    asm volatile("ldmatrix.sync.aligned.m8n8.x4.trans.shared.b16 {%0,%1,%2,%3}, [%4];\n"
                 : "=r"(r[0]), "=r"(r[1]), "=r"(r[2]), "=r"(r[3]) : "r"(addr));
}
__device__ __forceinline__ void mma16816(float* c, const uint32_t* a, uint32_t b0, uint32_t b1) {
    asm volatile("mma.sync.aligned.m16n8k16.row.col.f32.f16.f16.f32 "
                 "{%0,%1,%2,%3}, {%4,%5,%6,%7}, {%8,%9}, {%0,%1,%2,%3};\n"
                 : "+f"(c[0]), "+f"(c[1]), "+f"(c[2]), "+f"(c[3])
                 : "r"(a[0]), "r"(a[1]), "r"(a[2]), "r"(a[3]), "r"(b0), "r"(b1));
}

// fast transcendentals (MUFU-based); error ~1e-7, negligible vs fp16 GEMM error
__device__ __forceinline__ float fexp(float x)  { return __expf(x); }
__device__ __forceinline__ float flog(float x)  { return __logf(x); }
__device__ __forceinline__ float ftanh(float x) {
    // tanh(x) = 1 - 2/(exp(2x)+1), stable for all x (exp overflow -> inf -> 1)
    float e = __expf(2.0f * x);
    return 1.0f - 2.0f / (e + 1.0f);
}

// ---------------- conversion / packing kernels --------------------------------
// vectorized: one thread handles 8 output cols (KP0=384 = 48 groups of 8)
__global__ void convert_x(const float* __restrict__ x, __half* __restrict__ o)
{
    size_t g = (size_t)blockIdx.x * blockDim.x + threadIdx.x;   // group index
    const size_t total = (size_t)B_ROWS * (KP0 / 8);
    if (g >= total) return;
    int m  = (int)(g / (KP0 / 8));
    int k0 = (int)(g - (size_t)m * (KP0 / 8)) * 8;
    const float* xr = x + (size_t)m * S_DIM;
    __half h[8];
#pragma unroll
    for (int i = 0; i < 8; i++) {
        int k = k0 + i;
        h[i] = __float2half((k < S_DIM) ? xr[k] : 0.0f);
    }
    *reinterpret_cast<uint4*>(o + (size_t)m * KP0 + k0) = *reinterpret_cast<uint4*>(h);
}

__global__ void convert_w(const float* __restrict__ W, int K, int N,
                          __half* __restrict__ o, int KPd, int NBd)
{
    int idx = blockIdx.x * blockDim.x + threadIdx.x;
    if (idx >= KPd * NBd) return;
    int k = idx / NBd, n = idx - k * NBd;
    o[idx] = __float2half((k < K && n < N) ? W[(size_t)k * N + n] : 0.0f);
}

__global__ void pack_heads(const float* __restrict__ Wmu, const float* __restrict__ bmu,
                           const float* __restrict__ Wlv, const float* __restrict__ blv,
                           const float* __restrict__ Wu,  const float* __restrict__ bu,
                           const float* __restrict__ Ww,  const float* __restrict__ bw,
                           const float* __restrict__ Wb,  const float* __restrict__ bb)
{
    int idx = blockIdx.x * blockDim.x + threadIdx.x;
    if (idx < KP2 * NB3) {
        int k = idx / NB3, c = idx - k * NB3;
        float v = 0.0f;
        if (k < H2_DIM) {
            if      (c < 17)  v = Wmu[k * 17  + c];
            else if (c < 34)  v = Wlv[k * 17  + (c - 17)];
            else if (c < 289) v = Wu [k * 255 + (c - 34)];
            else if (c < 544) v = Ww [k * 255 + (c - 289)];
            else if (c < 559) v = Wb [k * 15  + (c - 544)];
        }
        g_Wh[idx] = __float2half(v);
    }
    if (idx < HEAD_N) {
        int c = idx;
        float v;
        if      (c < 17)  v = bmu[c];
        else if (c < 34)  v = blv[c - 17];
        else if (c < 289) v = bu [c - 34];
        else if (c < 544) v = bw [c - 289];
        else              v = bb [c - 544];
        g_bh[c] = v;
    }
}

// ---------------- tensor-core GEMM (mma.sync fp16, single term) ---------------
// Block tile 256(M) x 64(N) x 32(K); 8 warps: 4 over M x 2 over N, warp 64x32.
// 4-stage cp.async ring (20KB/stage = 80KB total -> 2 CTAs/SM).
#define STAGES 4
#define A_BYTES 16384
#define STAGE_BYTES 20480

template <int OUT>
__global__ __launch_bounds__(256, 2) void gemm_mma(
    const __half* __restrict__ A, int lda, int Kiter,
    const __half* __restrict__ B, int ldb,
    const float* __restrict__ bias, int N,
    float* __restrict__ Cf, __half* __restrict__ Ch, int ldc)
{
    extern __shared__ char smem[];
    const uint32_t sb = smem_u32(smem);

    const int tid  = threadIdx.x;
    const int lane = tid & 31;
    const int wid  = tid >> 5;
    const int wm   = wid & 3;      // 4 warps over M (64 rows each)
    const int wn   = wid >> 2;     // 2 warps over N (32 cols each)
    const int m0   = blockIdx.y * 256;
    const int n0   = blockIdx.x * 64;
    const int KT   = Kiter / 32;

    float acc[4][4][4];
#pragma unroll
    for (int i = 0; i < 4; i++)
#pragma unroll
        for (int j = 0; j < 4; j++)
#pragma unroll
            for (int q = 0; q < 4; q++) acc[i][j][q] = 0.0f;

    auto load_stage = [&](int s, int kt) {
        const uint32_t stA = sb + s * STAGE_BYTES;
        const uint32_t stB = stA + A_BYTES;
#pragma unroll
        for (int q = 0; q < 4; q++) {
            int g   = tid + 256 * q;
            int row = g >> 2;
            int c4  = g & 3;
            const __half* src = A + (size_t)(m0 + row) * lda + kt * 32 + c4 * 8;
            cp16(stA + row * 64 + ((c4 ^ ((row >> 1) & 3)) * 16), src);
        }
        {
            int row = tid >> 3;
            int c8  = tid & 7;
            const __half* src = B + (size_t)(kt * 32 + row) * ldb + n0 + c8 * 8;
            cp16(stB + row * 128 + ((c8 ^ (row & 7)) * 16), src);
        }
        cp_commit();
    };

    load_stage(0, 0);
    load_stage(1, 1);
    load_stage(2, 2);

    for (int c = 0; c < KT; c++) {
        const int s = c & (STAGES - 1);
        asm volatile("cp.async.wait_group 2;" ::: "memory");
        __syncthreads();

        if (c + 3 < KT) load_stage((c + 3) & (STAGES - 1), c + 3);
        else            cp_commit();

        const uint32_t stA = sb + s * STAGE_BYTES;
        const uint32_t stB = stA + A_BYTES;

#pragma unroll
        for (int kk = 0; kk < 2; kk++) {
            uint32_t ah[4][4], bh[2][4];
            {
                int rbase = (lane & 15);
                int q     = kk * 2 + (lane >> 4);   // 0..3
#pragma unroll
                for (int mi = 0; mi < 4; mi++) {
                    int r = wm * 64 + mi * 16 + rbase;
                    ldsm_x4(ah[mi], stA + r * 64 + ((q ^ ((r >> 1) & 3)) * 16));
                }
            }
            {
                int row  = kk * 16 + (lane & 15);
                int half = (lane >> 4);
#pragma unroll
                for (int ni = 0; ni < 2; ni++) {
                    int c8 = wn * 4 + ni * 2 + half;
                    ldsm_x4t(bh[ni], stB + row * 128 + ((c8 ^ (row & 7)) * 16));
                }
            }
#pragma unroll
            for (int mi = 0; mi < 4; mi++) {
#pragma unroll
                for (int n8 = 0; n8 < 4; n8++) {
                    int ni = n8 >> 1, j = (n8 & 1) * 2;
                    mma16816(acc[mi][n8], ah[mi], bh[ni][j], bh[ni][j + 1]);
                }
            }
        }
    }

    // ---- epilogue ----
    const int lr = lane >> 2;          // 0..7
    const int lc = (lane & 3) * 2;     // 0,2,4,6
#pragma unroll
    for (int mi = 0; mi < 4; mi++) {
#pragma unroll
        for (int n8 = 0; n8 < 4; n8++) {
            int col = n0 + wn * 32 + n8 * 8 + lc;
            float b0 = (col     < N) ? bias[col]     : 0.0f;
            float b1 = (col + 1 < N) ? bias[col + 1] : 0.0f;
#pragma unroll
            for (int h = 0; h < 2; h++) {
                int row = m0 + wm * 64 + mi * 16 + h * 8 + lr;
                float v0 = acc[mi][n8][2 * h + 0] + b0;
                float v1 = acc[mi][n8][2 * h + 1] + b1;
                if (OUT == 1) {
                    v0 = (col     < N) ? fmaxf(v0, 0.0f) : 0.0f;
                    v1 = (col + 1 < N) ? fmaxf(v1, 0.0f) : 0.0f;
                    __half2 hv; hv.x = __float2half(v0); hv.y = __float2half(v1);
                    *reinterpret_cast<__half2*>(&Ch[(size_t)row * ldc + col]) = hv;
                } else {
                    float2 f2; f2.x = v0; f2.y = v1;
                    *reinterpret_cast<float2*>(&Cf[(size_t)row * ldc + col]) = f2;
                }
            }
        }
    }
}

// ---------------- flow chain + sampling + log-prob epilogue ------------------
// 8 warps/block, one row per warp. Row staged into smem via coalesced float4
// loads, then flow math with MUFU-based transcendentals.
__global__ __launch_bounds__(256) void flow_kernel(
    const float* __restrict__ eps, float* __restrict__ out)
{
    __shared__ float rows[8][NB3];

    const int wid  = threadIdx.x >> 5;
    const int lane = threadIdx.x & 31;
    const int warp = blockIdx.x * 8 + wid;
    if (warp >= B_ROWS) return;

    // coalesced row staging: 576 floats = 144 float4, 32 lanes
    {
        const float4* src = reinterpret_cast<const float4*>(g_heads + (size_t)warp * NB3);
        float4* dst = reinterpret_cast<float4*>(rows[wid]);
#pragma unroll
        for (int i = lane; i < NB3 / 4; i += 32) dst[i] = src[i];
    }
    __syncwarp();

    const float* hr = rows[wid];
    const bool act = (lane < A_DIM);

    float mu = 0.0f, lv = 0.0f, e = 0.0f;
    if (act) {
        mu = ftanh(hr[lane]);
        lv = ftanh(hr[17 + lane]);
        e  = eps[(size_t)warp * A_DIM + lane];
    }
    float z = mu + fexp(lv) * e;
    float ldj = 0.0f;

#pragma unroll 3
    for (int k = 0; k < K_FLOWS; k++) {
        float u = 0.0f, w = 0.0f;
        if (act) {
            u = hr[34  + k * A_DIM + lane];
            w = hr[289 + k * A_DIM + lane];
        }
        float bk = hr[544 + k];

        float uw  = w * u;
        float wns = w * w;
        float wz  = w * z;
#pragma unroll
        for (int s = 16; s; s >>= 1) {
            uw  += __shfl_xor_sync(0xffffffffu, uw,  s);
            wns += __shfl_xor_sync(0xffffffffu, wns, s);
            wz  += __shfl_xor_sync(0xffffffffu, wz,  s);
        }
        // softplus(uw) = max(uw,0) + log(1 + exp(-|uw|))
        float sp   = fmaxf(uw, 0.0f) + flog(1.0f + fexp(-fabsf(uw)));
        float m_uw = -1.0f + sp;
        float scale = (m_uw - uw) / wns;
        float u_hat = u + scale * w;
        float t = ftanh(wz + bk);
        z += u_hat * t;
        float psi_u = m_uw * (1.0f - t * t);      // w . u_hat == m_uw analytically
        ldj += flog(fabsf(1.0f + psi_u));
    }

    if (act) out[(size_t)warp * A_DIM + lane] = z;

    float lp = act ? (-0.5f * e * e - lv) : 0.0f;
#pragma unroll
    for (int s = 16; s; s >>= 1) lp += __shfl_xor_sync(0xffffffffu, lp, s);
    lp -= 0.5f * (float)A_DIM * 1.8378770664093453f;

    if (lane == 0) {
        float lpf = lp - ldj;
        out[(size_t)B_ROWS * A_DIM + warp]          = fexp(lpf);
        out[(size_t)B_ROWS * A_DIM + B_ROWS + warp] = lpf;
    }
}

// ---------------- launch ------------------------------------------------------
extern "C" void kernel_launch(void* const* d_in, const int* in_sizes, int n_in,
                              void* d_out, int out_size)
{
    (void)in_sizes; (void)n_in; (void)out_size;

    const float* x   = (const float*)d_in[0];
    const float* eps = (const float*)d_in[1];
    const float* W1  = (const float*)d_in[2];
    const float* b1  = (const float*)d_in[3];
    const float* W2  = (const float*)d_in[4];
    const float* b2  = (const float*)d_in[5];
    const float* Wmu = (const float*)d_in[6];
    const float* bmu = (const float*)d_in[7];
    const float* Wlv = (const float*)d_in[8];
    const float* blv = (const float*)d_in[9];
    const float* Wu  = (const float*)d_in[10];
    const float* bu  = (const float*)d_in[11];
    const float* Ww  = (const float*)d_in[12];
    const float* bw  = (const float*)d_in[13];
    const float* Wb  = (const float*)d_in[14];
    const float* bb  = (const float*)d_in[15];
    float* out = (float*)d_out;

    __half *x16, *h1, *h2, *w1, *w2, *wh;
    float *hdp, *bhp;
    cudaGetSymbolAddress((void**)&x16, g_x16);
    cudaGetSymbolAddress((void**)&h1,  g_h1);
    cudaGetSymbolAddress((void**)&h2,  g_h2);
    cudaGetSymbolAddress((void**)&w1,  g_W1);
    cudaGetSymbolAddress((void**)&w2,  g_W2);
    cudaGetSymbolAddress((void**)&wh,  g_Wh);
    cudaGetSymbolAddress((void**)&hdp, g_heads);
    cudaGetSymbolAddress((void**)&bhp, g_bh);

    convert_x<<<(int)(((size_t)B_ROWS * (KP0 / 8) + 255) / 256), 256>>>(x, x16);
    convert_w<<<(KP0 * NB1 + 255) / 256, 256>>>(W1, S_DIM,  H1_DIM, w1, KP0, NB1);
    convert_w<<<(NB1 * NB2 + 255) / 256, 256>>>(W2, H1_DIM, H2_DIM, w2, NB1, NB2);
    pack_heads<<<(KP2 * NB3 + 255) / 256, 256>>>(Wmu, bmu, Wlv, blv, Wu, bu, Ww, bw, Wb, bb);

    const int smem_bytes = STAGES * STAGE_BYTES;   // 81920
    cudaFuncSetAttribute(gemm_mma<1>, cudaFuncAttributeMaxDynamicSharedMemorySize, smem_bytes);
    cudaFuncSetAttribute(gemm_mma<0>, cudaFuncAttributeMaxDynamicSharedMemorySize, smem_bytes);

    dim3 blk(256);
    // layer 1: [65536,384] x [384,448] -> h1 (relu)
    gemm_mma<1><<<dim3(NB1 / 64, B_ROWS / 256), blk, smem_bytes>>>(
        x16, KP0, KP0, w1, NB1, b1, H1_DIM, nullptr, h1, NB1);
    // layer 2: [65536,448(K=416)] x [448,320] -> h2 (relu)
    gemm_mma<1><<<dim3(NB2 / 64, B_ROWS / 256), blk, smem_bytes>>>(
        h1, NB1, KI1, w2, NB2, b2, H2_DIM, nullptr, h2, NB2);
    // heads: [65536,320] x [320,576] -> fp32
    gemm_mma<0><<<dim3(NB3 / 64, B_ROWS / 256), blk, smem_bytes>>>(
        h2, KP2, KP2, wh, NB3, bhp, HEAD_N, hdp, nullptr, NB3);

    flow_kernel<<<B_ROWS / 8, 256>>>(eps, out);
}

// round 8
// speedup vs baseline: 2.4044x; 1.0239x over previous
#include <cuda_runtime.h>
#include <cuda_fp16.h>
#include <math.h>
#include <stdint.h>

#define B_ROWS 65536
#define S_DIM  376
#define A_DIM  17
#define H1_DIM 400
#define H2_DIM 300
#define K_FLOWS 15
#define HEAD_N 559

#define KP0 384   // padded S_DIM
#define NB1 448   // padded H1_DIM  (= K stride of layer 2)
#define KI1 416   // K iterations for layer 2 (cols 400..415 zero, 416..447 skipped)
#define NB2 320   // padded H2_DIM  (= K of layer 3)
#define KP2 320
#define NB3 576   // padded HEAD_N

// ---------------- scratch (static device globals; no allocation) -------------
__device__ __half g_x16[(size_t)B_ROWS * KP0];
__device__ __half g_h1[(size_t)B_ROWS * NB1];
__device__ __half g_h2[(size_t)B_ROWS * NB2];
__device__ __half g_h3[(size_t)B_ROWS * NB3];   // heads, fp16 now

__device__ __half g_W1[KP0 * NB1];
__device__ __half g_W2[NB1 * NB2];
__device__ __half g_Wh[KP2 * NB3];
__device__ float  g_bh[HEAD_N];

// ---------------- small helpers ----------------------------------------------
__device__ __forceinline__ uint32_t smem_u32(const void* p) {
    return (uint32_t)__cvta_generic_to_shared(p);
}
__device__ __forceinline__ void cp16(uint32_t dst, const void* src) {
    asm volatile("cp.async.cg.shared.global [%0], [%1], 16;\n" :: "r"(dst), "l"(src));
}
__device__ __forceinline__ void cp_commit() {
    asm volatile("cp.async.commit_group;\n" ::);
}
__device__ __forceinline__ void ldsm_x4(uint32_t* r, uint32_t addr) {
    asm volatile("ldmatrix.sync.aligned.m8n8.x4.shared.b16 {%0,%1,%2,%3}, [%4];\n"
                 : "=r"(r[0]), "=r"(r[1]), "=r"(r[2]), "=r"(r[3]) : "r"(addr));
}
__device__ __forceinline__ void ldsm_x4t(uint32_t* r, uint32_t addr) {
    asm volatile("ldmatrix.sync.aligned.m8n8.x4.trans.shared.b16 {%0,%1,%2,%3}, [%4];\n"
                 : "=r"(r[0]), "=r"(r[1]), "=r"(r[2]), "=r"(r[3]) : "r"(addr));
}
__device__ __forceinline__ void mma16816(float* c, const uint32_t* a, uint32_t b0, uint32_t b1) {
    asm volatile("mma.sync.aligned.m16n8k16.row.col.f32.f16.f16.f32 "
                 "{%0,%1,%2,%3}, {%4,%5,%6,%7}, {%8,%9}, {%0,%1,%2,%3};\n"
                 : "+f"(c[0]), "+f"(c[1]), "+f"(c[2]), "+f"(c[3])
                 : "r"(a[0]), "r"(a[1]), "r"(a[2]), "r"(a[3]), "r"(b0), "r"(b1));
}

// fast transcendentals (MUFU-based)
__device__ __forceinline__ float fexp(float x)  { return __expf(x); }
__device__ __forceinline__ float flog(float x)  { return __logf(x); }
__device__ __forceinline__ float ftanh(float x) {
    float e = __expf(2.0f * x);
    return 1.0f - 2.0f / (e + 1.0f);
}

// ---------------- conversion / packing kernels --------------------------------
__global__ void convert_x(const float* __restrict__ x, __half* __restrict__ o)
{
    size_t g = (size_t)blockIdx.x * blockDim.x + threadIdx.x;
    const size_t total = (size_t)B_ROWS * (KP0 / 8);
    if (g >= total) return;
    int m  = (int)(g / (KP0 / 8));
    int k0 = (int)(g - (size_t)m * (KP0 / 8)) * 8;
    const float* xr = x + (size_t)m * S_DIM;
    __half h[8];
#pragma unroll
    for (int i = 0; i < 8; i++) {
        int k = k0 + i;
        h[i] = __float2half((k < S_DIM) ? xr[k] : 0.0f);
    }
    *reinterpret_cast<uint4*>(o + (size_t)m * KP0 + k0) = *reinterpret_cast<uint4*>(h);
}

// single kernel: W1, W2, packed heads, head bias
#define W1_ELEMS (KP0 * NB1)
#define W2_ELEMS (NB1 * NB2)
#define WH_ELEMS (KP2 * NB3)
__global__ void prep_weights(
    const float* __restrict__ W1,  const float* __restrict__ W2,
    const float* __restrict__ Wmu, const float* __restrict__ bmu,
    const float* __restrict__ Wlv, const float* __restrict__ blv,
    const float* __restrict__ Wu,  const float* __restrict__ bu,
    const float* __restrict__ Ww,  const float* __restrict__ bw,
    const float* __restrict__ Wb,  const float* __restrict__ bb)
{
    int idx = blockIdx.x * blockDim.x + threadIdx.x;
    if (idx < W1_ELEMS) {
        int k = idx / NB1, n = idx - k * NB1;
        g_W1[idx] = __float2half((k < S_DIM && n < H1_DIM) ? W1[(size_t)k * H1_DIM + n] : 0.0f);
    }
    int i2 = idx - W1_ELEMS;
    if (i2 >= 0 && i2 < W2_ELEMS) {
        int k = i2 / NB2, n = i2 - k * NB2;
        g_W2[i2] = __float2half((k < H1_DIM && n < H2_DIM) ? W2[(size_t)k * H2_DIM + n] : 0.0f);
    }
    int i3 = idx - (W1_ELEMS + W2_ELEMS);
    if (i3 >= 0 && i3 < WH_ELEMS) {
        int k = i3 / NB3, c = i3 - k * NB3;
        float v = 0.0f;
        if (k < H2_DIM) {
            if      (c < 17)  v = Wmu[k * 17  + c];
            else if (c < 34)  v = Wlv[k * 17  + (c - 17)];
            else if (c < 289) v = Wu [k * 255 + (c - 34)];
            else if (c < 544) v = Ww [k * 255 + (c - 289)];
            else if (c < 559) v = Wb [k * 15  + (c - 544)];
        }
        g_Wh[i3] = __float2half(v);
    }
    if (idx < HEAD_N) {
        int c = idx;
        float v;
        if      (c < 17)  v = bmu[c];
        else if (c < 34)  v = blv[c - 17];
        else if (c < 289) v = bu [c - 34];
        else if (c < 544) v = bw [c - 289];
        else              v = bb [c - 544];
        g_bh[c] = v;
    }
}

// ---------------- tensor-core GEMM (mma.sync fp16, single term) ---------------
// Block tile 256(M) x 64(N) x 32(K); 8 warps: 4 over M x 2 over N, warp 64x32.
// 5-stage cp.async ring (20KB/stage = 100KB -> 2 CTAs/SM), prefetch distance 4.
// OUT==1: bias+relu, fp16 out. OUT==0: bias only, fp16 out.
#define STAGES 5
#define A_BYTES 16384
#define STAGE_BYTES 20480

template <int OUT>
__global__ __launch_bounds__(256, 2) void gemm_mma(
    const __half* __restrict__ A, int lda, int Kiter,
    const __half* __restrict__ B, int ldb,
    const float* __restrict__ bias, int N,
    __half* __restrict__ Ch, int ldc)
{
    extern __shared__ char smem[];
    const uint32_t sb = smem_u32(smem);

    const int tid  = threadIdx.x;
    const int lane = tid & 31;
    const int wid  = tid >> 5;
    const int wm   = wid & 3;
    const int wn   = wid >> 2;
    const int m0   = blockIdx.y * 256;
    const int n0   = blockIdx.x * 64;
    const int KT   = Kiter / 32;

    float acc[4][4][4];
#pragma unroll
    for (int i = 0; i < 4; i++)
#pragma unroll
        for (int j = 0; j < 4; j++)
#pragma unroll
            for (int q = 0; q < 4; q++) acc[i][j][q] = 0.0f;

    auto load_stage = [&](int s, int kt) {
        const uint32_t stA = sb + s * STAGE_BYTES;
        const uint32_t stB = stA + A_BYTES;
#pragma unroll
        for (int q = 0; q < 4; q++) {
            int g   = tid + 256 * q;
            int row = g >> 2;
            int c4  = g & 3;
            const __half* src = A + (size_t)(m0 + row) * lda + kt * 32 + c4 * 8;
            cp16(stA + row * 64 + ((c4 ^ ((row >> 1) & 3)) * 16), src);
        }
        {
            int row = tid >> 3;
            int c8  = tid & 7;
            const __half* src = B + (size_t)(kt * 32 + row) * ldb + n0 + c8 * 8;
            cp16(stB + row * 128 + ((c8 ^ (row & 7)) * 16), src);
        }
        cp_commit();
    };

    load_stage(0, 0);
    load_stage(1, 1);
    load_stage(2, 2);
    load_stage(3, 3);

    int sc = 0, sp = 4;   // consume / prefetch ring positions
    for (int c = 0; c < KT; c++) {
        asm volatile("cp.async.wait_group 3;" ::: "memory");
        __syncthreads();

        if (c + 4 < KT) load_stage(sp, c + 4);
        else            cp_commit();
        if (++sp == STAGES) sp = 0;

        const uint32_t stA = sb + sc * STAGE_BYTES;
        const uint32_t stB = stA + A_BYTES;
        if (++sc == STAGES) sc = 0;

#pragma unroll
        for (int kk = 0; kk < 2; kk++) {
            uint32_t ah[4][4], bh[2][4];
            {
                int rbase = (lane & 15);
                int q     = kk * 2 + (lane >> 4);
#pragma unroll
                for (int mi = 0; mi < 4; mi++) {
                    int r = wm * 64 + mi * 16 + rbase;
                    ldsm_x4(ah[mi], stA + r * 64 + ((q ^ ((r >> 1) & 3)) * 16));
                }
            }
            {
                int row  = kk * 16 + (lane & 15);
                int half = (lane >> 4);
#pragma unroll
                for (int ni = 0; ni < 2; ni++) {
                    int c8 = wn * 4 + ni * 2 + half;
                    ldsm_x4t(bh[ni], stB + row * 128 + ((c8 ^ (row & 7)) * 16));
                }
            }
#pragma unroll
            for (int mi = 0; mi < 4; mi++) {
#pragma unroll
                for (int n8 = 0; n8 < 4; n8++) {
                    int ni = n8 >> 1, j = (n8 & 1) * 2;
                    mma16816(acc[mi][n8], ah[mi], bh[ni][j], bh[ni][j + 1]);
                }
            }
        }
    }

    // ---- epilogue: bias (+relu), fp16 store ----
    const int lr = lane >> 2;
    const int lc = (lane & 3) * 2;
#pragma unroll
    for (int mi = 0; mi < 4; mi++) {
#pragma unroll
        for (int n8 = 0; n8 < 4; n8++) {
            int col = n0 + wn * 32 + n8 * 8 + lc;
            float b0 = (col     < N) ? bias[col]     : 0.0f;
            float b1 = (col + 1 < N) ? bias[col + 1] : 0.0f;
#pragma unroll
            for (int h = 0; h < 2; h++) {
                int row = m0 + wm * 64 + mi * 16 + h * 8 + lr;
                float v0 = acc[mi][n8][2 * h + 0] + b0;
                float v1 = acc[mi][n8][2 * h + 1] + b1;
                if (OUT == 1) {
                    v0 = (col     < N) ? fmaxf(v0, 0.0f) : 0.0f;
                    v1 = (col + 1 < N) ? fmaxf(v1, 0.0f) : 0.0f;
                }
                __half2 hv; hv.x = __float2half(v0); hv.y = __float2half(v1);
                *reinterpret_cast<__half2*>(&Ch[(size_t)row * ldc + col]) = hv;
            }
        }
    }
}

// ---------------- flow chain + sampling + log-prob epilogue ------------------
// 8 warps/block, one row per warp; fp16 heads row staged to smem as fp32.
__global__ __launch_bounds__(256) void flow_kernel(
    const float* __restrict__ eps, float* __restrict__ out)
{
    __shared__ float rows[8][NB3];

    const int wid  = threadIdx.x >> 5;
    const int lane = threadIdx.x & 31;
    const int warp = blockIdx.x * 8 + wid;
    if (warp >= B_ROWS) return;

    // stage: 576 halves = 72 x uint4(8 halves), coalesced
    {
        const uint4* src = reinterpret_cast<const uint4*>(g_h3 + (size_t)warp * NB3);
#pragma unroll
        for (int i = lane; i < NB3 / 8; i += 32) {
            uint4 v = src[i];
            const __half* hp = reinterpret_cast<const __half*>(&v);
#pragma unroll
            for (int j = 0; j < 8; j++) rows[wid][i * 8 + j] = __half2float(hp[j]);
        }
    }
    __syncwarp();

    const float* hr = rows[wid];
    const bool act = (lane < A_DIM);

    float mu = 0.0f, lv = 0.0f, e = 0.0f;
    if (act) {
        mu = ftanh(hr[lane]);
        lv = ftanh(hr[17 + lane]);
        e  = eps[(size_t)warp * A_DIM + lane];
    }
    float z = mu + fexp(lv) * e;
    float ldj = 0.0f;

#pragma unroll 3
    for (int k = 0; k < K_FLOWS; k++) {
        float u = 0.0f, w = 0.0f;
        if (act) {
            u = hr[34  + k * A_DIM + lane];
            w = hr[289 + k * A_DIM + lane];
        }
        float bk = hr[544 + k];

        float uw  = w * u;
        float wns = w * w;
        float wz  = w * z;
#pragma unroll
        for (int s = 16; s; s >>= 1) {
            uw  += __shfl_xor_sync(0xffffffffu, uw,  s);
            wns += __shfl_xor_sync(0xffffffffu, wns, s);
            wz  += __shfl_xor_sync(0xffffffffu, wz,  s);
        }
        float sp   = fmaxf(uw, 0.0f) + flog(1.0f + fexp(-fabsf(uw)));
        float m_uw = -1.0f + sp;
        float scale = (m_uw - uw) / wns;
        float u_hat = u + scale * w;
        float t = ftanh(wz + bk);
        z += u_hat * t;
        float psi_u = m_uw * (1.0f - t * t);
        ldj += flog(fabsf(1.0f + psi_u));
    }

    if (act) out[(size_t)warp * A_DIM + lane] = z;

    float lp = act ? (-0.5f * e * e - lv) : 0.0f;
#pragma unroll
    for (int s = 16; s; s >>= 1) lp += __shfl_xor_sync(0xffffffffu, lp, s);
    lp -= 0.5f * (float)A_DIM * 1.8378770664093453f;

    if (lane == 0) {
        float lpf = lp - ldj;
        out[(size_t)B_ROWS * A_DIM + warp]          = fexp(lpf);
        out[(size_t)B_ROWS * A_DIM + B_ROWS + warp] = lpf;
    }
}

// ---------------- launch ------------------------------------------------------
extern "C" void kernel_launch(void* const* d_in, const int* in_sizes, int n_in,
                              void* d_out, int out_size)
{
    (void)in_sizes; (void)n_in; (void)out_size;

    const float* x   = (const float*)d_in[0];
    const float* eps = (const float*)d_in[1];
    const float* W1  = (const float*)d_in[2];
    const float* b1  = (const float*)d_in[3];
    const float* W2  = (const float*)d_in[4];
    const float* b2  = (const float*)d_in[5];
    const float* Wmu = (const float*)d_in[6];
    const float* bmu = (const float*)d_in[7];
    const float* Wlv = (const float*)d_in[8];
    const float* blv = (const float*)d_in[9];
    const float* Wu  = (const float*)d_in[10];
    const float* bu  = (const float*)d_in[11];
    const float* Ww  = (const float*)d_in[12];
    const float* bw  = (const float*)d_in[13];
    const float* Wb  = (const float*)d_in[14];
    const float* bb  = (const float*)d_in[15];
    float* out = (float*)d_out;

    __half *x16, *h1, *h2, *h3, *w1, *w2, *wh;
    float *bhp;
    cudaGetSymbolAddress((void**)&x16, g_x16);
    cudaGetSymbolAddress((void**)&h1,  g_h1);
    cudaGetSymbolAddress((void**)&h2,  g_h2);
    cudaGetSymbolAddress((void**)&h3,  g_h3);
    cudaGetSymbolAddress((void**)&w1,  g_W1);
    cudaGetSymbolAddress((void**)&w2,  g_W2);
    cudaGetSymbolAddress((void**)&wh,  g_Wh);
    cudaGetSymbolAddress((void**)&bhp, g_bh);

    convert_x<<<(int)(((size_t)B_ROWS * (KP0 / 8) + 255) / 256), 256>>>(x, x16);
    const int prep_total = W1_ELEMS + W2_ELEMS + WH_ELEMS;
    prep_weights<<<(prep_total + 255) / 256, 256>>>(W1, W2, Wmu, bmu, Wlv, blv,
                                                    Wu, bu, Ww, bw, Wb, bb);

    const int smem_bytes = STAGES * STAGE_BYTES;   // 102400
    cudaFuncSetAttribute(gemm_mma<1>, cudaFuncAttributeMaxDynamicSharedMemorySize, smem_bytes);
    cudaFuncSetAttribute(gemm_mma<0>, cudaFuncAttributeMaxDynamicSharedMemorySize, smem_bytes);

    dim3 blk(256);
    gemm_mma<1><<<dim3(NB1 / 64, B_ROWS / 256), blk, smem_bytes>>>(
        x16, KP0, KP0, w1, NB1, b1, H1_DIM, h1, NB1);
    gemm_mma<1><<<dim3(NB2 / 64, B_ROWS / 256), blk, smem_bytes>>>(
        h1, NB1, KI1, w2, NB2, b2, H2_DIM, h2, NB2);
    gemm_mma<0><<<dim3(NB3 / 64, B_ROWS / 256), blk, smem_bytes>>>(
        h2, KP2, KP2, wh, NB3, bhp, HEAD_N, h3, NB3);

    flow_kernel<<<B_ROWS / 8, 256>>>(eps, out);
}